// round 1
// baseline (speedup 1.0000x reference)
#include <cuda_runtime.h>
#include <math.h>

#define BB 2
#define SS 2048
#define DD 1024
#define HH 16
#define HD 64
#define M_TOT (BB*SS)   // 4096

// Scratch (allocation-free per harness rules)
__device__ float g_Q[M_TOT * DD];
__device__ float g_K[M_TOT * DD];
__device__ float g_V[M_TOT * DD];
__device__ float g_ctx[M_TOT * DD];

// ---------------------------------------------------------------------------
// C[M,N] = A[M,K] @ W[K,N] + bias[N]   (row-major, M%64==0, N%64==0, K%16==0)
// 64x64 tile, BK=16, 256 threads (16x16), 4x4 per thread.
// ---------------------------------------------------------------------------
__global__ void gemm_bias_kernel(const float* __restrict__ A,
                                 const float* __restrict__ W,
                                 const float* __restrict__ bias,
                                 float* __restrict__ C,
                                 int M, int N, int K) {
    __shared__ float As[16][65];   // As[kk][row] (+1 pad: conflict-free store)
    __shared__ float Ws[16][64];   // Ws[kk][col]

    const int tx = threadIdx.x, ty = threadIdx.y;
    const int tid = ty * 16 + tx;
    const int m0 = blockIdx.y * 64;
    const int n0 = blockIdx.x * 64;

    float acc[4][4] = {};

    for (int k0 = 0; k0 < K; k0 += 16) {
        // Load A tile: 64 rows x 16 k  (coalesced 16-wide per row)
        #pragma unroll
        for (int i = 0; i < 4; i++) {
            int idx = tid + i * 256;
            int r = idx >> 4, c = idx & 15;
            As[c][r] = A[(size_t)(m0 + r) * K + k0 + c];
        }
        // Load W tile: 16 k x 64 cols (coalesced 64-wide per row)
        #pragma unroll
        for (int i = 0; i < 4; i++) {
            int idx = tid + i * 256;
            int r = idx >> 6, c = idx & 63;
            Ws[r][c] = W[(size_t)(k0 + r) * N + n0 + c];
        }
        __syncthreads();

        #pragma unroll
        for (int kk = 0; kk < 16; kk++) {
            float a[4], b[4];
            #pragma unroll
            for (int i = 0; i < 4; i++) a[i] = As[kk][ty * 4 + i];
            #pragma unroll
            for (int j = 0; j < 4; j++) b[j] = Ws[kk][tx * 4 + j];
            #pragma unroll
            for (int i = 0; i < 4; i++)
                #pragma unroll
                for (int j = 0; j < 4; j++)
                    acc[i][j] = fmaf(a[i], b[j], acc[i][j]);
        }
        __syncthreads();
    }

    #pragma unroll
    for (int i = 0; i < 4; i++) {
        int row = m0 + ty * 4 + i;
        #pragma unroll
        for (int j = 0; j < 4; j++) {
            int col = n0 + tx * 4 + j;
            C[(size_t)row * N + col] = acc[i][j] + bias[col];
        }
    }
}

// ---------------------------------------------------------------------------
// Causal flash attention. One CTA per (b, h, 64-row q tile).
// 256 threads (16x16), each owns a 4x4 patch of the 64x64 score/output tiles.
// ---------------------------------------------------------------------------
#define LDP 65   // padded row stride in SMEM

__global__ void attn_kernel() {
    extern __shared__ float sm[];
    float (*Qs)[LDP] = (float(*)[LDP])(sm);
    float (*Ks)[LDP] = (float(*)[LDP])(sm + 64 * LDP);
    float (*Vs)[LDP] = (float(*)[LDP])(sm + 2 * 64 * LDP);
    float (*Ps)[LDP] = (float(*)[LDP])(sm + 3 * 64 * LDP);

    const int tx = threadIdx.x, ty = threadIdx.y;
    const int tid = ty * 16 + tx;
    const int qt = blockIdx.x;       // q tile index, 0..31
    const int h  = blockIdx.y;
    const int b  = blockIdx.z;
    const int q0 = qt * 64;
    const float scale = 0.125f;      // 1/sqrt(64)

    // Load Q tile (pre-scaled)
    #pragma unroll
    for (int i = 0; i < 16; i++) {
        int idx = tid + i * 256;
        int r = idx >> 6, c = idx & 63;
        Qs[r][c] = g_Q[(size_t)(b * SS + q0 + r) * DD + h * HD + c] * scale;
    }

    float m[4], l[4], o[4][4];
    #pragma unroll
    for (int i = 0; i < 4; i++) {
        m[i] = -INFINITY; l[i] = 0.f;
        #pragma unroll
        for (int j = 0; j < 4; j++) o[i][j] = 0.f;
    }

    for (int kt = 0; kt <= qt; kt++) {
        const int k0 = kt * 64;
        __syncthreads();   // previous P@V done before reloading K/V
        #pragma unroll
        for (int i = 0; i < 16; i++) {
            int idx = tid + i * 256;
            int r = idx >> 6, c = idx & 63;
            size_t g = (size_t)(b * SS + k0 + r) * DD + h * HD + c;
            Ks[r][c] = g_K[g];
            Vs[r][c] = g_V[g];
        }
        __syncthreads();

        // s = Q K^T (64x64), 4x4 per thread
        float s[4][4] = {};
        #pragma unroll
        for (int d = 0; d < 64; d++) {
            float a[4], bb[4];
            #pragma unroll
            for (int i = 0; i < 4; i++) a[i] = Qs[ty * 4 + i][d];
            #pragma unroll
            for (int j = 0; j < 4; j++) bb[j] = Ks[tx * 4 + j][d];
            #pragma unroll
            for (int i = 0; i < 4; i++)
                #pragma unroll
                for (int j = 0; j < 4; j++)
                    s[i][j] = fmaf(a[i], bb[j], s[i][j]);
        }

        if (kt == qt) {   // diagonal tile: mask cols > row
            #pragma unroll
            for (int i = 0; i < 4; i++)
                #pragma unroll
                for (int j = 0; j < 4; j++)
                    if (tx * 4 + j > ty * 4 + i) s[i][j] = -INFINITY;
        }

        // Online softmax update (row reductions across the 16 x-lanes)
        #pragma unroll
        for (int i = 0; i < 4; i++) {
            float mx = s[i][0];
            #pragma unroll
            for (int j = 1; j < 4; j++) mx = fmaxf(mx, s[i][j]);
            #pragma unroll
            for (int off = 8; off > 0; off >>= 1)
                mx = fmaxf(mx, __shfl_xor_sync(0xffffffffu, mx, off));
            float mnew = fmaxf(m[i], mx);
            float alpha = __expf(m[i] - mnew);
            float p[4], ls = 0.f;
            #pragma unroll
            for (int j = 0; j < 4; j++) { p[j] = __expf(s[i][j] - mnew); ls += p[j]; }
            #pragma unroll
            for (int off = 8; off > 0; off >>= 1)
                ls += __shfl_xor_sync(0xffffffffu, ls, off);
            l[i] = l[i] * alpha + ls;
            m[i] = mnew;
            #pragma unroll
            for (int j = 0; j < 4; j++) o[i][j] *= alpha;
            #pragma unroll
            for (int j = 0; j < 4; j++) Ps[ty * 4 + i][tx * 4 + j] = p[j];
        }
        __syncthreads();

        // O += P @ V
        #pragma unroll
        for (int d = 0; d < 64; d++) {
            float p[4], v[4];
            #pragma unroll
            for (int i = 0; i < 4; i++) p[i] = Ps[ty * 4 + i][d];
            #pragma unroll
            for (int j = 0; j < 4; j++) v[j] = Vs[d][tx * 4 + j];
            #pragma unroll
            for (int i = 0; i < 4; i++)
                #pragma unroll
                for (int j = 0; j < 4; j++)
                    o[i][j] = fmaf(p[i], v[j], o[i][j]);
        }
    }

    // Normalize and write ctx in (b, s, h, hd) layout
    #pragma unroll
    for (int i = 0; i < 4; i++) {
        float inv = 1.f / l[i];
        int row = b * SS + q0 + ty * 4 + i;
        #pragma unroll
        for (int j = 0; j < 4; j++)
            g_ctx[(size_t)row * DD + h * HD + tx * 4 + j] = o[i][j] * inv;
    }
}

// ---------------------------------------------------------------------------
extern "C" void kernel_launch(void* const* d_in, const int* in_sizes, int n_in,
                              void* d_out, int out_size) {
    const float* x  = (const float*)d_in[0];
    const float* Wq = (const float*)d_in[1];
    const float* bq = (const float*)d_in[2];
    const float* Wk = (const float*)d_in[3];
    const float* bk = (const float*)d_in[4];
    const float* Wv = (const float*)d_in[5];
    const float* bv = (const float*)d_in[6];
    const float* Wo = (const float*)d_in[7];
    const float* bo = (const float*)d_in[8];
    float* out = (float*)d_out;

    float *Qp, *Kp, *Vp, *Cp;
    cudaGetSymbolAddress((void**)&Qp, g_Q);
    cudaGetSymbolAddress((void**)&Kp, g_K);
    cudaGetSymbolAddress((void**)&Vp, g_V);
    cudaGetSymbolAddress((void**)&Cp, g_ctx);

    dim3 thr(16, 16);
    dim3 ggrid(DD / 64, M_TOT / 64);

    gemm_bias_kernel<<<ggrid, thr>>>(x, Wq, bq, Qp, M_TOT, DD, DD);
    gemm_bias_kernel<<<ggrid, thr>>>(x, Wk, bk, Kp, M_TOT, DD, DD);
    gemm_bias_kernel<<<ggrid, thr>>>(x, Wv, bv, Vp, M_TOT, DD, DD);

    size_t smem = 4 * 64 * LDP * sizeof(float);   // 66,560 B
    cudaFuncSetAttribute(attn_kernel, cudaFuncAttributeMaxDynamicSharedMemorySize, (int)smem);
    attn_kernel<<<dim3(SS / 64, HH, BB), thr, smem>>>();

    gemm_bias_kernel<<<ggrid, thr>>>(Cp, Wo, bo, out, M_TOT, DD, DD);
}

// round 3
// speedup vs baseline: 1.5866x; 1.5866x over previous
#include <cuda_runtime.h>
#include <cuda_bf16.h>
#include <cstdint>
#include <math.h>

#define BB 2
#define SS 2048
#define DD 1024
#define HH 16
#define HD 64
#define M_TOT (BB*SS)   // 4096

// ---------------------------------------------------------------------------
// Scratch (__device__ globals: allocation-free per harness rules)
// ---------------------------------------------------------------------------
__device__ float g_Q[M_TOT * DD];
__device__ float g_K[M_TOT * DD];
__device__ float g_V[M_TOT * DD];
__device__ float g_ctx[M_TOT * DD];

__device__ __nv_bfloat16 g_xhi[M_TOT * DD];
__device__ __nv_bfloat16 g_xlo[M_TOT * DD];
__device__ __nv_bfloat16 g_chi[M_TOT * DD];
__device__ __nv_bfloat16 g_clo[M_TOT * DD];

__device__ __nv_bfloat16 g_wq_hi[DD * DD];
__device__ __nv_bfloat16 g_wq_lo[DD * DD];
__device__ __nv_bfloat16 g_wk_hi[DD * DD];
__device__ __nv_bfloat16 g_wk_lo[DD * DD];
__device__ __nv_bfloat16 g_wv_hi[DD * DD];
__device__ __nv_bfloat16 g_wv_lo[DD * DD];
__device__ __nv_bfloat16 g_wo_hi[DD * DD];
__device__ __nv_bfloat16 g_wo_lo[DD * DD];

// ---------------------------------------------------------------------------
// helpers
// ---------------------------------------------------------------------------
__device__ __forceinline__ uint32_t smem_u32(const void* p) {
    uint32_t a;
    asm("{ .reg .u64 t; cvta.to.shared.u64 t, %1; cvt.u32.u64 %0, t; }" : "=r"(a) : "l"(p));
    return a;
}

__device__ __forceinline__ void ldmatrix_x4(uint32_t& r0, uint32_t& r1, uint32_t& r2,
                                            uint32_t& r3, uint32_t addr) {
    asm volatile("ldmatrix.sync.aligned.m8n8.x4.shared.b16 {%0,%1,%2,%3}, [%4];"
                 : "=r"(r0), "=r"(r1), "=r"(r2), "=r"(r3) : "r"(addr));
}
__device__ __forceinline__ void ldmatrix_x2(uint32_t& r0, uint32_t& r1, uint32_t addr) {
    asm volatile("ldmatrix.sync.aligned.m8n8.x2.shared.b16 {%0,%1}, [%2];"
                 : "=r"(r0), "=r"(r1) : "r"(addr));
}
__device__ __forceinline__ void mma_bf16(float* d, const uint32_t* a, const uint32_t* b) {
    asm volatile(
        "mma.sync.aligned.m16n8k16.row.col.f32.bf16.bf16.f32 "
        "{%0,%1,%2,%3}, {%4,%5,%6,%7}, {%8,%9}, {%0,%1,%2,%3};"
        : "+f"(d[0]), "+f"(d[1]), "+f"(d[2]), "+f"(d[3])
        : "r"(a[0]), "r"(a[1]), "r"(a[2]), "r"(a[3]), "r"(b[0]), "r"(b[1]));
}

// ---------------------------------------------------------------------------
// fp32 -> bf16 hi/lo split (elementwise, vectorized)
// ---------------------------------------------------------------------------
__global__ void cvt_split4(const float4* __restrict__ in,
                           __nv_bfloat162* __restrict__ hi,
                           __nv_bfloat162* __restrict__ lo, int n4) {
    int i = blockIdx.x * blockDim.x + threadIdx.x;
    if (i >= n4) return;
    float4 v = in[i];
    __nv_bfloat16 h0 = __float2bfloat16(v.x);
    __nv_bfloat16 h1 = __float2bfloat16(v.y);
    __nv_bfloat16 h2 = __float2bfloat16(v.z);
    __nv_bfloat16 h3 = __float2bfloat16(v.w);
    __nv_bfloat16 l0 = __float2bfloat16(v.x - __bfloat162float(h0));
    __nv_bfloat16 l1 = __float2bfloat16(v.y - __bfloat162float(h1));
    __nv_bfloat16 l2 = __float2bfloat16(v.z - __bfloat162float(h2));
    __nv_bfloat16 l3 = __float2bfloat16(v.w - __bfloat162float(h3));
    hi[2*i]   = __nv_bfloat162{h0, h1};
    hi[2*i+1] = __nv_bfloat162{h2, h3};
    lo[2*i]   = __nv_bfloat162{l0, l1};
    lo[2*i+1] = __nv_bfloat162{l2, l3};
}

// ---------------------------------------------------------------------------
// W[K][N] fp32 -> transposed bf16 hi/lo [N][K]
// ---------------------------------------------------------------------------
__global__ void cvt_wT(const float* __restrict__ W,
                       __nv_bfloat16* __restrict__ hiT,
                       __nv_bfloat16* __restrict__ loT) {
    __shared__ float t[32][33];
    int n0 = blockIdx.x * 32, k0 = blockIdx.y * 32;
    int tx = threadIdx.x, ty = threadIdx.y;
    #pragma unroll
    for (int r = 0; r < 32; r += 8)
        t[ty + r][tx] = W[(size_t)(k0 + ty + r) * DD + n0 + tx];
    __syncthreads();
    #pragma unroll
    for (int r = 0; r < 32; r += 8) {
        float v = t[tx][ty + r];                 // v = W[k0+tx][n0+ty+r]
        __nv_bfloat16 h = __float2bfloat16(v);
        __nv_bfloat16 l = __float2bfloat16(v - __bfloat162float(h));
        size_t o = (size_t)(n0 + ty + r) * DD + k0 + tx;   // [n][k]
        hiT[o] = h; loT[o] = l;
    }
}

// ---------------------------------------------------------------------------
// HMMA (mma.sync) GEMM: C[M,N] = A[M,K] @ W[K,N] + bias.
// A as bf16 hi/lo row-major [M][K]; B pre-transposed bf16 hi/lo [N][K].
// CTA tile 128x128, 8 warps (2x4), warp tile 64x32, k-chunk 32.
// 3-term bf16 split accumulated in fp32.
// ---------------------------------------------------------------------------
#define CTA_M 128
#define CTA_N 128
#define KC 32
#define LDT 40                      // padded smem row stride (elements)
#define TILE_ELEMS (128 * LDT)      // per-tile smem elements

__global__ void __launch_bounds__(256) gemm_hmma(
    const __nv_bfloat16* __restrict__ Ahi, const __nv_bfloat16* __restrict__ Alo,
    const __nv_bfloat16* __restrict__ BhiT, const __nv_bfloat16* __restrict__ BloT,
    const float* __restrict__ bias, float* __restrict__ C,
    int M, int N, int K) {
    __shared__ __nv_bfloat16 smAhi[TILE_ELEMS];
    __shared__ __nv_bfloat16 smAlo[TILE_ELEMS];
    __shared__ __nv_bfloat16 smBhi[TILE_ELEMS];
    __shared__ __nv_bfloat16 smBlo[TILE_ELEMS];

    const int tid  = threadIdx.x;
    const int wid  = tid >> 5;
    const int lane = tid & 31;
    const int warp_m = wid & 1;      // 0..1  (64 rows each)
    const int warp_n = wid >> 1;     // 0..3  (32 cols each)
    const int m0 = blockIdx.y * CTA_M;
    const int n0 = blockIdx.x * CTA_N;

    float acc[4][4][4];
    #pragma unroll
    for (int i = 0; i < 4; i++)
        #pragma unroll
        for (int j = 0; j < 4; j++)
            #pragma unroll
            for (int e = 0; e < 4; e++) acc[i][j][e] = 0.f;

    const uint32_t sAhi = smem_u32(smAhi), sAlo = smem_u32(smAlo);
    const uint32_t sBhi = smem_u32(smBhi), sBlo = smem_u32(smBlo);

    // per-lane ldmatrix base offsets
    const int lm_r  = lane & 7;
    const int lm_m4 = lane >> 3;        // 0..3 (matrix id for x4)
    const int a_row = warp_m * 64 + (lm_m4 & 1) * 8 + lm_r;   // + i*16
    const int a_kof = (lm_m4 >> 1) * 8;                       // + ks*16
    const int lm_m2 = (lane >> 3) & 1;
    const int b_row = warp_n * 32 + lm_r;                     // + j*8
    const int b_kof = lm_m2 * 8;                              // + ks*16

    for (int k0 = 0; k0 < K; k0 += KC) {
        // --- load 4 tiles: 128 rows x 32 bf16 each, uint4 (8 bf16) grain ---
        #pragma unroll
        for (int t = 0; t < 2; t++) {
            int idx = tid + t * 256;          // 0..511
            int row = idx >> 2, s = idx & 3;  // s: 8-elem sector
            int so = row * LDT + s * 8;
            *(uint4*)&smAhi[so] = *(const uint4*)(Ahi + (size_t)(m0 + row) * K + k0 + s * 8);
            *(uint4*)&smAlo[so] = *(const uint4*)(Alo + (size_t)(m0 + row) * K + k0 + s * 8);
            *(uint4*)&smBhi[so] = *(const uint4*)(BhiT + (size_t)(n0 + row) * K + k0 + s * 8);
            *(uint4*)&smBlo[so] = *(const uint4*)(BloT + (size_t)(n0 + row) * K + k0 + s * 8);
        }
        __syncthreads();

        #pragma unroll
        for (int ks = 0; ks < 2; ks++) {
            uint32_t ahi[4][4], alo[4][4], bhi[4][2], blo[4][2];
            #pragma unroll
            for (int i = 0; i < 4; i++) {
                uint32_t off = (uint32_t)((a_row + i * 16) * LDT + ks * 16 + a_kof) * 2;
                ldmatrix_x4(ahi[i][0], ahi[i][1], ahi[i][2], ahi[i][3], sAhi + off);
                ldmatrix_x4(alo[i][0], alo[i][1], alo[i][2], alo[i][3], sAlo + off);
            }
            #pragma unroll
            for (int j = 0; j < 4; j++) {
                uint32_t off = (uint32_t)((b_row + j * 8) * LDT + ks * 16 + b_kof) * 2;
                ldmatrix_x2(bhi[j][0], bhi[j][1], sBhi + off);
                ldmatrix_x2(blo[j][0], blo[j][1], sBlo + off);
            }
            #pragma unroll
            for (int i = 0; i < 4; i++)
                #pragma unroll
                for (int j = 0; j < 4; j++) {
                    mma_bf16(acc[i][j], ahi[i], bhi[j]);
                    mma_bf16(acc[i][j], ahi[i], blo[j]);
                    mma_bf16(acc[i][j], alo[i], bhi[j]);
                }
        }
        __syncthreads();
    }

    // --- epilogue: D frag (m16n8): d0,d1 row grp cols 2tg,2tg+1; d2,d3 row grp+8
    const int grp = lane >> 2, tg = lane & 3;
    #pragma unroll
    for (int i = 0; i < 4; i++) {
        int row0 = m0 + warp_m * 64 + i * 16 + grp;
        #pragma unroll
        for (int j = 0; j < 4; j++) {
            int col = n0 + warp_n * 32 + j * 8 + tg * 2;
            float b0 = bias[col], b1 = bias[col + 1];
            float* p0 = C + (size_t)row0 * N + col;
            p0[0] = acc[i][j][0] + b0;
            p0[1] = acc[i][j][1] + b1;
            float* p1 = C + (size_t)(row0 + 8) * N + col;
            p1[0] = acc[i][j][2] + b0;
            p1[1] = acc[i][j][3] + b1;
        }
    }
}

// ---------------------------------------------------------------------------
// Causal flash attention (unchanged — fp32 FFMA)
// ---------------------------------------------------------------------------
#define LDP 65

__global__ void attn_kernel() {
    extern __shared__ float sm[];
    float (*Qs)[LDP] = (float(*)[LDP])(sm);
    float (*Ks)[LDP] = (float(*)[LDP])(sm + 64 * LDP);
    float (*Vs)[LDP] = (float(*)[LDP])(sm + 2 * 64 * LDP);
    float (*Ps)[LDP] = (float(*)[LDP])(sm + 3 * 64 * LDP);

    const int tx = threadIdx.x, ty = threadIdx.y;
    const int tid = ty * 16 + tx;
    const int qt = blockIdx.x;
    const int h  = blockIdx.y;
    const int b  = blockIdx.z;
    const int q0 = qt * 64;
    const float scale = 0.125f;

    #pragma unroll
    for (int i = 0; i < 16; i++) {
        int idx = tid + i * 256;
        int r = idx >> 6, c = idx & 63;
        Qs[r][c] = g_Q[(size_t)(b * SS + q0 + r) * DD + h * HD + c] * scale;
    }

    float m[4], l[4], o[4][4];
    #pragma unroll
    for (int i = 0; i < 4; i++) {
        m[i] = -INFINITY; l[i] = 0.f;
        #pragma unroll
        for (int j = 0; j < 4; j++) o[i][j] = 0.f;
    }

    for (int kt = 0; kt <= qt; kt++) {
        const int k0 = kt * 64;
        __syncthreads();
        #pragma unroll
        for (int i = 0; i < 16; i++) {
            int idx = tid + i * 256;
            int r = idx >> 6, c = idx & 63;
            size_t g = (size_t)(b * SS + k0 + r) * DD + h * HD + c;
            Ks[r][c] = g_K[g];
            Vs[r][c] = g_V[g];
        }
        __syncthreads();

        float s[4][4] = {};
        #pragma unroll
        for (int d = 0; d < 64; d++) {
            float a[4], bb[4];
            #pragma unroll
            for (int i = 0; i < 4; i++) a[i] = Qs[ty * 4 + i][d];
            #pragma unroll
            for (int j = 0; j < 4; j++) bb[j] = Ks[tx * 4 + j][d];
            #pragma unroll
            for (int i = 0; i < 4; i++)
                #pragma unroll
                for (int j = 0; j < 4; j++)
                    s[i][j] = fmaf(a[i], bb[j], s[i][j]);
        }

        if (kt == qt) {
            #pragma unroll
            for (int i = 0; i < 4; i++)
                #pragma unroll
                for (int j = 0; j < 4; j++)
                    if (tx * 4 + j > ty * 4 + i) s[i][j] = -INFINITY;
        }

        #pragma unroll
        for (int i = 0; i < 4; i++) {
            float mx = s[i][0];
            #pragma unroll
            for (int j = 1; j < 4; j++) mx = fmaxf(mx, s[i][j]);
            #pragma unroll
            for (int off = 8; off > 0; off >>= 1)
                mx = fmaxf(mx, __shfl_xor_sync(0xffffffffu, mx, off));
            float mnew = fmaxf(m[i], mx);
            float alpha = __expf(m[i] - mnew);
            float p[4], ls = 0.f;
            #pragma unroll
            for (int j = 0; j < 4; j++) { p[j] = __expf(s[i][j] - mnew); ls += p[j]; }
            #pragma unroll
            for (int off = 8; off > 0; off >>= 1)
                ls += __shfl_xor_sync(0xffffffffu, ls, off);
            l[i] = l[i] * alpha + ls;
            m[i] = mnew;
            #pragma unroll
            for (int j = 0; j < 4; j++) o[i][j] *= alpha;
            #pragma unroll
            for (int j = 0; j < 4; j++) Ps[ty * 4 + i][tx * 4 + j] = p[j];
        }
        __syncthreads();

        #pragma unroll
        for (int d = 0; d < 64; d++) {
            float p[4], v[4];
            #pragma unroll
            for (int i = 0; i < 4; i++) p[i] = Ps[ty * 4 + i][d];
            #pragma unroll
            for (int j = 0; j < 4; j++) v[j] = Vs[d][tx * 4 + j];
            #pragma unroll
            for (int i = 0; i < 4; i++)
                #pragma unroll
                for (int j = 0; j < 4; j++)
                    o[i][j] = fmaf(p[i], v[j], o[i][j]);
        }
    }

    #pragma unroll
    for (int i = 0; i < 4; i++) {
        float inv = 1.f / l[i];
        int row = b * SS + q0 + ty * 4 + i;
        #pragma unroll
        for (int j = 0; j < 4; j++)
            g_ctx[(size_t)row * DD + h * HD + tx * 4 + j] = o[i][j] * inv;
    }
}

// ---------------------------------------------------------------------------
extern "C" void kernel_launch(void* const* d_in, const int* in_sizes, int n_in,
                              void* d_out, int out_size) {
    const float* x  = (const float*)d_in[0];
    const float* Wq = (const float*)d_in[1];
    const float* bq = (const float*)d_in[2];
    const float* Wk = (const float*)d_in[3];
    const float* bk = (const float*)d_in[4];
    const float* Wv = (const float*)d_in[5];
    const float* bv = (const float*)d_in[6];
    const float* Wo = (const float*)d_in[7];
    const float* bo = (const float*)d_in[8];
    float* out = (float*)d_out;

    float *Qp, *Kp, *Vp, *Cp;
    cudaGetSymbolAddress((void**)&Qp, g_Q);
    cudaGetSymbolAddress((void**)&Kp, g_K);
    cudaGetSymbolAddress((void**)&Vp, g_V);
    cudaGetSymbolAddress((void**)&Cp, g_ctx);
    __nv_bfloat16 *xhi, *xlo, *chi, *clo;
    cudaGetSymbolAddress((void**)&xhi, g_xhi);
    cudaGetSymbolAddress((void**)&xlo, g_xlo);
    cudaGetSymbolAddress((void**)&chi, g_chi);
    cudaGetSymbolAddress((void**)&clo, g_clo);
    __nv_bfloat16 *wqh, *wql, *wkh, *wkl, *wvh, *wvl, *woh, *wol;
    cudaGetSymbolAddress((void**)&wqh, g_wq_hi);
    cudaGetSymbolAddress((void**)&wql, g_wq_lo);
    cudaGetSymbolAddress((void**)&wkh, g_wk_hi);
    cudaGetSymbolAddress((void**)&wkl, g_wk_lo);
    cudaGetSymbolAddress((void**)&wvh, g_wv_hi);
    cudaGetSymbolAddress((void**)&wvl, g_wv_lo);
    cudaGetSymbolAddress((void**)&woh, g_wo_hi);
    cudaGetSymbolAddress((void**)&wol, g_wo_lo);

    // 1) split conversions
    int n4 = M_TOT * DD / 4;
    cvt_split4<<<(n4 + 255) / 256, 256>>>((const float4*)x,
                                          (__nv_bfloat162*)xhi, (__nv_bfloat162*)xlo, n4);
    dim3 wtg(DD / 32, DD / 32), wtb(32, 8);
    cvt_wT<<<wtg, wtb>>>(Wq, wqh, wql);
    cvt_wT<<<wtg, wtb>>>(Wk, wkh, wkl);
    cvt_wT<<<wtg, wtb>>>(Wv, wvh, wvl);
    cvt_wT<<<wtg, wtb>>>(Wo, woh, wol);

    // 2) QKV projections on HMMA tensor cores
    dim3 gg(DD / CTA_N, M_TOT / CTA_M);   // (8, 32)
    gemm_hmma<<<gg, 256>>>(xhi, xlo, wqh, wql, bq, Qp, M_TOT, DD, DD);
    gemm_hmma<<<gg, 256>>>(xhi, xlo, wkh, wkl, bk, Kp, M_TOT, DD, DD);
    gemm_hmma<<<gg, 256>>>(xhi, xlo, wvh, wvl, bv, Vp, M_TOT, DD, DD);

    // 3) attention (fp32, unchanged)
    size_t smem = 4 * 64 * LDP * sizeof(float);
    cudaFuncSetAttribute(attn_kernel, cudaFuncAttributeMaxDynamicSharedMemorySize, (int)smem);
    attn_kernel<<<dim3(SS / 64, HH, BB), dim3(16, 16), smem>>>();

    // 4) output projection
    cvt_split4<<<(n4 + 255) / 256, 256>>>((const float4*)Cp,
                                          (__nv_bfloat162*)chi, (__nv_bfloat162*)clo, n4);
    gemm_hmma<<<gg, 256>>>(chi, clo, woh, wol, bo, out, M_TOT, DD, DD);
}